// round 1
// baseline (speedup 1.0000x reference)
#include <cuda_runtime.h>

#define NB 8
#define NC 16
#define NH 512
#define NW 512
#define NHW (NH * NW)

// Channel-last accumulator scratch: [B, H, W, C]  (134 MB, static device mem — allowed)
__device__ float g_scr[(size_t)NB * NHW * NC];

// ---------------------------------------------------------------------------
// Kernel 1: zero the scratch (graph replays accumulate otherwise)
// ---------------------------------------------------------------------------
__global__ void k_zero() {
    size_t i = (size_t)blockIdx.x * blockDim.x + threadIdx.x;
    ((float4*)g_scr)[i] = make_float4(0.f, 0.f, 0.f, 0.f);
}

// ---------------------------------------------------------------------------
// Kernel 2: forward-warp scatter with vectorized global reductions
// ---------------------------------------------------------------------------
__device__ __forceinline__ void red4(float* p, float a, float b, float c, float d) {
    asm volatile("red.global.add.v4.f32 [%0], {%1,%2,%3,%4};"
                 :: "l"(p), "f"(a), "f"(b), "f"(c), "f"(d) : "memory");
}

__global__ void k_scatter(const float* __restrict__ im0,
                          const float* __restrict__ flow) {
    int x = blockIdx.x * blockDim.x + threadIdx.x;   // 0..511
    int y = blockIdx.y;
    int b = blockIdx.z;

    int pix = (b * NH + y) * NW + x;
    float2 f = __ldg((const float2*)flow + pix);

    float xd = (float)x + f.x;
    float yd = (float)y + f.y;
    float x0f = floorf(xd), y0f = floorf(yd);
    int x0 = (int)x0f, y0 = (int)y0f;

    // Reference: scatter only if ALL four corners in-bounds
    if (x0 < 0 || x0 > NW - 2 || y0 < 0 || y0 > NH - 2) return;

    float fx = xd - x0f, fy = yd - y0f;
    float wnw = (1.f - fx) * (1.f - fy);
    float wne = fx * (1.f - fy);
    float wsw = (1.f - fx) * fy;
    float wse = fx * fy;

    // Gather 16 channels (coalesced per channel across the warp)
    float v[NC];
    const float* src = im0 + (size_t)b * NC * NHW + (size_t)y * NW + x;
#pragma unroll
    for (int c = 0; c < NC; ++c) v[c] = __ldg(src + (size_t)c * NHW);

    float* nw = g_scr + ((size_t)(b * NH + y0) * NW + x0) * NC;
    float* ne = nw + NC;
    float* sw = nw + (size_t)NW * NC;
    float* se = sw + NC;

#pragma unroll
    for (int k = 0; k < 4; ++k) {
        float a0 = v[4 * k + 0], a1 = v[4 * k + 1], a2 = v[4 * k + 2], a3 = v[4 * k + 3];
        red4(nw + 4 * k, a0 * wnw, a1 * wnw, a2 * wnw, a3 * wnw);
        red4(ne + 4 * k, a0 * wne, a1 * wne, a2 * wne, a3 * wne);
        red4(sw + 4 * k, a0 * wsw, a1 * wsw, a2 * wsw, a3 * wsw);
        red4(se + 4 * k, a0 * wse, a1 * wse, a2 * wse, a3 * wse);
    }
}

// ---------------------------------------------------------------------------
// Kernel 3: transpose [B,H,W,C] scratch -> [B,C,H,W] output, fused + im1
// ---------------------------------------------------------------------------
__global__ void k_transpose(const float* __restrict__ im1,
                            float* __restrict__ out) {
    __shared__ float s[NC][257];
    int b = blockIdx.y;
    int pbase = blockIdx.x * 256;
    int t = threadIdx.x;

    // Each thread loads its pixel's 16 channels (4 x float4, contiguous 64B)
    const float4* src = (const float4*)(g_scr + ((size_t)b * NHW + pbase + t) * NC);
#pragma unroll
    for (int i = 0; i < 4; ++i) {
        float4 vv = src[i];
        s[4 * i + 0][t] = vv.x;
        s[4 * i + 1][t] = vv.y;
        s[4 * i + 2][t] = vv.z;
        s[4 * i + 3][t] = vv.w;
    }
    __syncthreads();

    size_t obase = (size_t)b * NC * NHW + pbase + t;
#pragma unroll
    for (int c = 0; c < NC; ++c) {
        size_t idx = obase + (size_t)c * NHW;
        out[idx] = s[c][t] + __ldg(im1 + idx);
    }
}

// ---------------------------------------------------------------------------
extern "C" void kernel_launch(void* const* d_in, const int* in_sizes, int n_in,
                              void* d_out, int out_size) {
    const float* im0  = (const float*)d_in[0];
    const float* flow = (const float*)d_in[1];
    const float* im1  = (const float*)d_in[2];
    float* out = (float*)d_out;

    // scratch floats = 8*512*512*16 = 33,554,432 -> 8,388,608 float4
    k_zero<<<8388608 / 256, 256>>>();
    k_scatter<<<dim3(NW / 256, NH, NB), 256>>>(im0, flow);
    k_transpose<<<dim3(NHW / 256, NB), 256>>>(im1, out);
}